// round 12
// baseline (speedup 1.0000x reference)
#include <cuda_runtime.h>
#include <cuda_bf16.h>
#include <cstdint>

#define BB 8
#define TT 2048
#define DD 1024
#define MT (BB * TT)   // 16384 rows

// ---------------- scratch (__device__ globals; no allocs allowed) -----------
__device__ float g_q[(size_t)MT * DD];
__device__ float g_k[(size_t)MT * DD];
__device__ float g_v[(size_t)MT * DD];
__device__ __nv_bfloat16 g_xhi[(size_t)MT * DD];
__device__ __nv_bfloat16 g_xlo[(size_t)MT * DD];
__device__ __nv_bfloat16 g_whi[3][(size_t)DD * DD];   // stacked q,k,v -> rows 0..3071
__device__ __nv_bfloat16 g_wlo[3][(size_t)DD * DD];
// scan intermediates
#define NCH 16
#define LCH 128
__device__ float g_finals[NCH * BB * DD];
__device__ float g_carries[NCH * BB * DD];

// ---------------- helpers ----------------------------------------------------
__device__ __forceinline__ uint32_t smem_to_u32(const void* p) {
    uint32_t a;
    asm("{ .reg .u64 t; cvta.to.shared.u64 t, %1; cvt.u32.u64 %0, t; }"
        : "=r"(a) : "l"(p));
    return a;
}
__device__ __forceinline__ void cp_async16(uint32_t saddr, const void* gptr) {
    asm volatile("cp.async.cg.shared.global [%0], [%1], 16;\n"
                 :: "r"(saddr), "l"(gptr));
}
__device__ __forceinline__ void cp_commit() {
    asm volatile("cp.async.commit_group;\n" ::: "memory");
}
__device__ __forceinline__ void cp_wait1() {
    asm volatile("cp.async.wait_group 1;\n" ::: "memory");
}
__device__ __forceinline__ void cp_wait0() {
    asm volatile("cp.async.wait_group 0;\n" ::: "memory");
}
__device__ __forceinline__ void ldm_x4(uint32_t* r, uint32_t addr) {
    asm volatile("ldmatrix.sync.aligned.m8n8.x4.shared.b16 {%0,%1,%2,%3}, [%4];"
                 : "=r"(r[0]), "=r"(r[1]), "=r"(r[2]), "=r"(r[3]) : "r"(addr));
}
__device__ __forceinline__ void mma_bf16(float* c, const uint32_t* a, const uint32_t* b) {
    asm volatile("mma.sync.aligned.m16n8k16.row.col.f32.bf16.bf16.f32 "
                 "{%0,%1,%2,%3}, {%4,%5,%6,%7}, {%8,%9}, {%0,%1,%2,%3};"
                 : "+f"(c[0]), "+f"(c[1]), "+f"(c[2]), "+f"(c[3])
                 : "r"(a[0]), "r"(a[1]), "r"(a[2]), "r"(a[3]),
                   "r"(b[0]), "r"(b[1]));
}

// ---------------- split fp32 -> bf16 hi/lo ----------------------------------
__global__ __launch_bounds__(256) void split_kernel(const float* __restrict__ src,
                                                    __nv_bfloat16* __restrict__ hi,
                                                    __nv_bfloat16* __restrict__ lo,
                                                    int n4) {
    int i = blockIdx.x * blockDim.x + threadIdx.x;
    if (i >= n4) return;
    float4 v = ((const float4*)src)[i];
    __nv_bfloat16 h[4], l[4];
    float f[4] = {v.x, v.y, v.z, v.w};
#pragma unroll
    for (int j = 0; j < 4; j++) {
        h[j] = __float2bfloat16_rn(f[j]);
        l[j] = __float2bfloat16_rn(f[j] - __bfloat162float(h[j]));
    }
    ((uint2*)hi)[i] = *(uint2*)h;
    ((uint2*)lo)[i] = *(uint2*)l;
}

// ---------------- fused QKV HMMA bf16 split GEMM -----------------------------
// C_seg[M,1024] = (Ahi+Alo)[M,K] @ (Whi+Wlo)[3072,K]^T (3 terms) + bias_seg
// Block tile 128x256, BK=32, 16 warps (2m x 8n), warp tile 64x32.
// 512 threads -> 4 warps/SMSP for latency hiding.
#define ASTR 40                    // padded row stride in bf16 elements
#define ROWB (ASTR * 2)            // 80 bytes
#define ST_A_HI 0
#define ST_A_LO (128 * ROWB)               // 10240
#define ST_B_HI (2 * 128 * ROWB)           // 20480
#define ST_B_LO (ST_B_HI + 256 * ROWB)     // 40960
#define STAGE_B (ST_B_LO + 256 * ROWB)     // 61440
#define NSTAGE 3
#define NCHK (DD / 32)             // 32 chunks
#define GTHREADS 512

__global__ __launch_bounds__(GTHREADS, 1) void gemm_qkv_kernel(
    const __nv_bfloat16* __restrict__ Ahi, const __nv_bfloat16* __restrict__ Alo,
    const __nv_bfloat16* __restrict__ Whi, const __nv_bfloat16* __restrict__ Wlo,
    const float* __restrict__ bq, const float* __restrict__ bk,
    const float* __restrict__ bv,
    float* __restrict__ Cq, float* __restrict__ Ck, float* __restrict__ Cv) {
    extern __shared__ char smem[];
    const uint32_t smem_base = smem_to_u32(smem);
    const int tid = threadIdx.x;
    const int wid = tid >> 5;
    const int lane = tid & 31;
    const int warp_m = wid & 1;          // 2 warps in M (64 rows each)
    const int warp_n = wid >> 1;         // 8 warps in N (32 cols each)
    const int bm = blockIdx.y * 128;
    const int bn = blockIdx.x * 256;     // 0..3071 within stacked W
    const int seg = bn >> 10;            // 0=q, 1=k, 2=v
    const int cn = bn & (DD - 1);        // column base within segment

    const float* bias = (seg == 0) ? bq : (seg == 1) ? bk : bv;
    float* C = (seg == 0) ? Cq : (seg == 1) ? Ck : Cv;

    // ldmatrix lane-address components
    const int lr = lane & 7;
    const int g = lane >> 3;                       // 0..3
    const uint32_t a_row = warp_m * 64 + (g & 1) * 8 + lr;   // + mt*16
    const uint32_t a_koff = (g >> 1) * 8;
    const uint32_t b_row = warp_n * 32 + ((lane >> 4) << 3) + lr;  // + j*16
    const uint32_t b_koff = ((lane >> 3) & 1) * 8;

    float acc[4][4][4];
#pragma unroll
    for (int i = 0; i < 4; i++)
#pragma unroll
        for (int j = 0; j < 4; j++)
#pragma unroll
            for (int r = 0; r < 4; r++) acc[i][j][r] = 0.f;

    // ---- async tile loader (512 threads) ------------------------------------
    auto issue_load = [&](int ch) {
        const uint32_t sbase = smem_base + (ch % NSTAGE) * STAGE_B;
        const int k0 = ch * 32;
        {
            const __nv_bfloat16* sh = Ahi + (size_t)bm * DD + k0;
            const __nv_bfloat16* sl = Alo + (size_t)bm * DD + k0;
            // 128 rows x 4 segs = 512 -> one per thread
            const int r = tid >> 2, segi = tid & 3;
            cp_async16(sbase + ST_A_HI + r * ROWB + segi * 16,
                       sh + (size_t)r * DD + segi * 8);
            cp_async16(sbase + ST_A_LO + r * ROWB + segi * 16,
                       sl + (size_t)r * DD + segi * 8);
        }
        {
            const __nv_bfloat16* sh = Whi + (size_t)bn * DD + k0;
            const __nv_bfloat16* sl = Wlo + (size_t)bn * DD + k0;
            // 256 rows x 4 segs = 1024 -> two per thread
#pragma unroll
            for (int rep = 0; rep < 2; rep++) {
                const int idx = tid + rep * GTHREADS;   // 0..1023
                const int r = idx >> 2, segi = idx & 3;
                cp_async16(sbase + ST_B_HI + r * ROWB + segi * 16,
                           sh + (size_t)r * DD + segi * 8);
                cp_async16(sbase + ST_B_LO + r * ROWB + segi * 16,
                           sl + (size_t)r * DD + segi * 8);
            }
        }
        cp_commit();
    };

    issue_load(0);
    issue_load(1);

    for (int ch = 0; ch < NCHK; ch++) {
        if (ch == NCHK - 1) cp_wait0(); else cp_wait1();
        __syncthreads();
        if (ch + 2 < NCHK) issue_load(ch + 2);

        const uint32_t base = smem_base + (ch % NSTAGE) * STAGE_B;
#pragma unroll
        for (int ks = 0; ks < 2; ks++) {
            uint32_t ahi[4][4], alo[4][4], bhi[2][4], blo[2][4];
#pragma unroll
            for (int mt = 0; mt < 4; mt++) {
                uint32_t ar = base + (a_row + mt * 16) * ROWB
                            + (ks * 16 + a_koff) * 2;
                ldm_x4(ahi[mt], ar + ST_A_HI);
                ldm_x4(alo[mt], ar + ST_A_LO);
            }
#pragma unroll
            for (int j = 0; j < 2; j++) {             // each covers 2 n-tiles
                uint32_t br = base + (b_row + j * 16) * ROWB
                            + (ks * 16 + b_koff) * 2;
                ldm_x4(bhi[j], br + ST_B_HI);
                ldm_x4(blo[j], br + ST_B_LO);
            }
#pragma unroll
            for (int mt = 0; mt < 4; mt++)
#pragma unroll
                for (int nt = 0; nt < 4; nt++)
                    mma_bf16(acc[mt][nt], ahi[mt], &bhi[nt >> 1][(nt & 1) * 2]);
#pragma unroll
            for (int mt = 0; mt < 4; mt++)
#pragma unroll
                for (int nt = 0; nt < 4; nt++)
                    mma_bf16(acc[mt][nt], ahi[mt], &blo[nt >> 1][(nt & 1) * 2]);
#pragma unroll
            for (int mt = 0; mt < 4; mt++)
#pragma unroll
                for (int nt = 0; nt < 4; nt++)
                    mma_bf16(acc[mt][nt], alo[mt], &bhi[nt >> 1][(nt & 1) * 2]);
        }
    }

    // ---- epilogue: direct frag stores + bias --------------------------------
    const int qr = lane >> 2;           // 0..7
    const int qc = (lane & 3) * 2;      // 0,2,4,6
#pragma unroll
    for (int mt = 0; mt < 4; mt++) {
#pragma unroll
        for (int nt = 0; nt < 4; nt++) {
            const int row0 = bm + warp_m * 64 + mt * 16 + qr;
            const int col = cn + warp_n * 32 + nt * 8 + qc;
            const float2 bvv = *(const float2*)&bias[col];
            float2 v0, v1;
            v0.x = acc[mt][nt][0] + bvv.x;
            v0.y = acc[mt][nt][1] + bvv.y;
            v1.x = acc[mt][nt][2] + bvv.x;
            v1.y = acc[mt][nt][3] + bvv.y;
            *(float2*)&C[(size_t)row0 * DD + col] = v0;
            *(float2*)&C[(size_t)(row0 + 8) * DD + col] = v1;
        }
    }
}

// ---------------- chunked scan (kv = k*v computed inline) --------------------
__global__ __launch_bounds__(256) void scan1_kernel(const float* __restrict__ decay) {
    int x = blockIdx.x * blockDim.x + threadIdx.x;   // < NCH*BB*DD
    int d = x & (DD - 1);
    int b = (x >> 10) & (BB - 1);
    int c = x >> 13;
    float dec = decay[d];
    size_t base = (size_t)b * TT * DD + (size_t)c * LCH * DD + d;
    float mem = 0.f;
#pragma unroll 4
    for (int t = 0; t < LCH; t++) {
        size_t off = base + (size_t)t * DD;
        mem = fmaf(dec, mem, g_k[off] * g_v[off]);
    }
    g_finals[((size_t)c * BB + b) * DD + d] = mem;
}

__global__ __launch_bounds__(256) void scan2_kernel(const float* __restrict__ decay) {
    int x = blockIdx.x * blockDim.x + threadIdx.x;   // < BB*DD
    int d = x & (DD - 1);
    int b = x >> 10;
    float dec = decay[d];
    float pL = dec;
#pragma unroll
    for (int i = 0; i < 7; i++) pL *= pL;            // dec^128
    float carry = 0.f;
#pragma unroll
    for (int c = 0; c < NCH; c++) {
        size_t idx = ((size_t)c * BB + b) * DD + d;
        g_carries[idx] = carry;
        carry = fmaf(pL, carry, g_finals[idx]);
    }
}

__global__ __launch_bounds__(256) void scan3_kernel(const float* __restrict__ decay,
                                                    float* __restrict__ out) {
    int x = blockIdx.x * blockDim.x + threadIdx.x;
    int d = x & (DD - 1);
    int b = (x >> 10) & (BB - 1);
    int c = x >> 13;
    float dec = decay[d];
    size_t base = (size_t)b * TT * DD + (size_t)c * LCH * DD + d;
    float mem = g_carries[((size_t)c * BB + b) * DD + d];
#pragma unroll 4
    for (int t = 0; t < LCH; t++) {
        size_t off = base + (size_t)t * DD;
        mem = fmaf(dec, mem, g_k[off] * g_v[off]);
        out[off] = g_q[off] * mem;
    }
}

// ---------------- launch -----------------------------------------------------
extern "C" void kernel_launch(void* const* d_in, const int* in_sizes, int n_in,
                              void* d_out, int out_size) {
    const float* x     = (const float*)d_in[0];
    const float* Wq    = (const float*)d_in[1];
    const float* bq    = (const float*)d_in[2];
    const float* Wk    = (const float*)d_in[3];
    const float* bk    = (const float*)d_in[4];
    const float* Wv    = (const float*)d_in[5];
    const float* bv    = (const float*)d_in[6];
    const float* decay = (const float*)d_in[7];
    float* out = (float*)d_out;

    float *q_p, *k_p, *v_p;
    __nv_bfloat16 *xhi_p, *xlo_p, *whi_p, *wlo_p;
    cudaGetSymbolAddress((void**)&q_p, g_q);
    cudaGetSymbolAddress((void**)&k_p, g_k);
    cudaGetSymbolAddress((void**)&v_p, g_v);
    cudaGetSymbolAddress((void**)&xhi_p, g_xhi);
    cudaGetSymbolAddress((void**)&xlo_p, g_xlo);
    cudaGetSymbolAddress((void**)&whi_p, g_whi);
    cudaGetSymbolAddress((void**)&wlo_p, g_wlo);

    const size_t WN = (size_t)DD * DD;

    // hi/lo splits
    split_kernel<<<(MT * DD / 4) / 256, 256>>>(x, xhi_p, xlo_p, MT * DD / 4);
    split_kernel<<<(int)(WN / 4) / 256, 256>>>(Wq, whi_p + 0 * WN, wlo_p + 0 * WN, (int)(WN / 4));
    split_kernel<<<(int)(WN / 4) / 256, 256>>>(Wk, whi_p + 1 * WN, wlo_p + 1 * WN, (int)(WN / 4));
    split_kernel<<<(int)(WN / 4) / 256, 256>>>(Wv, whi_p + 2 * WN, wlo_p + 2 * WN, (int)(WN / 4));

    // fused QKV HMMA GEMM (single launch, N=3072, 512 threads/CTA)
    const int smem_bytes = NSTAGE * STAGE_B;   // 184320
    cudaFuncSetAttribute(gemm_qkv_kernel, cudaFuncAttributeMaxDynamicSharedMemorySize, smem_bytes);
    dim3 grid(3 * DD / 256, MT / 128);         // (12, 128) = 1536 CTAs
    gemm_qkv_kernel<<<grid, GTHREADS, smem_bytes>>>(xhi_p, xlo_p, whi_p, wlo_p,
                                                    bq, bk, bv, q_p, k_p, v_p);

    // chunked scan
    scan1_kernel<<<(NCH * BB * DD) / 256, 256>>>(decay);
    scan2_kernel<<<(BB * DD) / 256, 256>>>(decay);
    scan3_kernel<<<(NCH * BB * DD) / 256, 256>>>(decay, out);
}

// round 13
// speedup vs baseline: 1.9053x; 1.9053x over previous
#include <cuda_runtime.h>
#include <cuda_bf16.h>
#include <cstdint>

#define BB 8
#define TT 2048
#define DD 1024
#define MT (BB * TT)   // 16384 rows

#define TILE_PK 10240               // one packed tile: 128 rows x 80 B
#define XBLK 128                    // x row-blocks (MT/128)
#define WBLK 24                     // stacked W row-blocks (3072/128)
#define NCHK 32                     // K chunks of 32

// ---------------- scratch (__device__ globals; no allocs allowed) -----------
__device__ float g_q[(size_t)MT * DD];
__device__ float g_k[(size_t)MT * DD];
__device__ float g_v[(size_t)MT * DD];
__device__ uint8_t g_xpack_hi[(size_t)XBLK * NCHK * TILE_PK];   // 40 MB
__device__ uint8_t g_xpack_lo[(size_t)XBLK * NCHK * TILE_PK];
__device__ uint8_t g_wpack_hi[(size_t)WBLK * NCHK * TILE_PK];   // 7.5 MB
__device__ uint8_t g_wpack_lo[(size_t)WBLK * NCHK * TILE_PK];
// scan intermediates
#define NCH 16
#define LCH 128
__device__ float g_finals[NCH * BB * DD];
__device__ float g_carries[NCH * BB * DD];

// ---------------- helpers ----------------------------------------------------
__device__ __forceinline__ uint32_t smem_to_u32(const void* p) {
    uint32_t a;
    asm("{ .reg .u64 t; cvta.to.shared.u64 t, %1; cvt.u32.u64 %0, t; }"
        : "=r"(a) : "l"(p));
    return a;
}
__device__ __forceinline__ void cp_bulk(uint32_t sdst, const void* gsrc,
                                        uint32_t bytes, uint32_t mbar) {
    asm volatile("cp.async.bulk.shared::cta.global.mbarrier::complete_tx::bytes "
                 "[%0], [%1], %2, [%3];"
                 :: "r"(sdst), "l"(gsrc), "r"(bytes), "r"(mbar) : "memory");
}
#define MBARRIER_INIT(mbar, count) \
    asm volatile("mbarrier.init.shared.b64 [%0], %1;" \
                 :: "r"((uint32_t)(mbar)), "r"((uint32_t)(count)) : "memory")
#define MBARRIER_EXPECT_TX(mbar, bytes) \
    asm volatile("mbarrier.arrive.expect_tx.shared.b64 _, [%0], %1;" \
                 :: "r"((uint32_t)(mbar)), "r"((uint32_t)(bytes)) : "memory")
#define MBARRIER_WAIT_PARITY(mbar_smem_addr, phase_parity) do { \
    uint32_t _mbar = (uint32_t)(mbar_smem_addr); \
    uint32_t _parity = (uint32_t)(phase_parity); \
    uint32_t _done; \
    asm volatile("{\n\t.reg .pred p;\n\t" \
        "mbarrier.try_wait.parity.acquire.cta.shared::cta.b64 p, [%1], %2;\n\t" \
        "selp.b32 %0, 1, 0, p;\n\t}" : "=r"(_done) : "r"(_mbar), "r"(_parity) : "memory"); \
    if (!_done) { \
        asm volatile("{\n\t.reg .pred P1;\n\t" \
            "WAIT_LOOP_%=:\n\t" \
            "mbarrier.try_wait.parity.acquire.cta.shared::cta.b64 P1, [%0], %1, 0x989680;\n\t" \
            "@P1 bra.uni WAIT_DONE_%=;\n\t" \
            "bra.uni WAIT_LOOP_%=;\n\t" \
            "WAIT_DONE_%=:\n\t}" :: "r"(_mbar), "r"(_parity) : "memory"); \
    } \
} while (0)
__device__ __forceinline__ void ldm_x4(uint32_t* r, uint32_t addr) {
    asm volatile("ldmatrix.sync.aligned.m8n8.x4.shared.b16 {%0,%1,%2,%3}, [%4];"
                 : "=r"(r[0]), "=r"(r[1]), "=r"(r[2]), "=r"(r[3]) : "r"(addr));
}
__device__ __forceinline__ void mma_bf16(float* c, const uint32_t* a, const uint32_t* b) {
    asm volatile("mma.sync.aligned.m16n8k16.row.col.f32.bf16.bf16.f32 "
                 "{%0,%1,%2,%3}, {%4,%5,%6,%7}, {%8,%9}, {%0,%1,%2,%3};"
                 : "+f"(c[0]), "+f"(c[1]), "+f"(c[2]), "+f"(c[3])
                 : "r"(a[0]), "r"(a[1]), "r"(a[2]), "r"(a[3]),
                   "r"(b[0]), "r"(b[1]));
}

// ---------------- split fp32 -> bf16 hi/lo, packed tile layout ---------------
// dst layout: tile (rowblock rb, chunk ch) = contiguous 10240 B:
//   row (r & 127) at +row*80, col (c & 31) bf16 at +col*2.
__global__ __launch_bounds__(256) void split_pack_kernel(const float* __restrict__ src,
                                                         uint8_t* __restrict__ hi,
                                                         uint8_t* __restrict__ lo,
                                                         int n4) {
    int i = blockIdx.x * blockDim.x + threadIdx.x;
    if (i >= n4) return;
    int r = i >> 8;               // global row (256 float4 per row)
    int c = (i & 255) << 2;       // starting col
    float4 v = ((const float4*)src)[i];
    __nv_bfloat16 h[4], l[4];
    float f[4] = {v.x, v.y, v.z, v.w};
#pragma unroll
    for (int j = 0; j < 4; j++) {
        h[j] = __float2bfloat16_rn(f[j]);
        l[j] = __float2bfloat16_rn(f[j] - __bfloat162float(h[j]));
    }
    size_t off = (size_t)((r >> 7) * NCHK + (c >> 5)) * TILE_PK
               + (size_t)(r & 127) * 80 + (size_t)((c & 31) << 1);
    *(uint2*)(hi + off) = *(uint2*)h;
    *(uint2*)(lo + off) = *(uint2*)l;
}

// ---------------- fused QKV HMMA bf16 split GEMM, bulk-async loads -----------
// C_seg[M,1024] = (Ahi+Alo)[M,K] @ (Whi+Wlo)[3072,K]^T (3 terms) + bias_seg
// Block tile 128x256, BK=32, 8 warps (2m x 4n), warp tile 64x64, 256 threads.
// 3-stage smem ring fed by 6 cp.async.bulk per chunk, mbarrier completion.
#define ROWB 80
#define ST_A_HI 0
#define ST_A_LO (128 * ROWB)               // 10240
#define ST_B_HI (2 * 128 * ROWB)           // 20480 (2 tiles)
#define ST_B_LO (ST_B_HI + 256 * ROWB)     // 40960 (2 tiles)
#define STAGE_B (ST_B_LO + 256 * ROWB)     // 61440
#define NSTAGE 3
#define SM_MBAR (NSTAGE * STAGE_B)         // mbarriers after stages

__global__ __launch_bounds__(256, 1) void gemm_qkv_kernel(
    const float* __restrict__ bq, const float* __restrict__ bk,
    const float* __restrict__ bv,
    float* __restrict__ Cq, float* __restrict__ Ck, float* __restrict__ Cv) {
    extern __shared__ char smem[];
    const uint32_t smem_base = smem_to_u32(smem);
    const int tid = threadIdx.x;
    const int wid = tid >> 5;
    const int lane = tid & 31;
    const int warp_m = wid & 1;          // 2 warps in M (64 rows each)
    const int warp_n = wid >> 1;         // 4 warps in N (64 cols each)
    const int bm = blockIdx.y * 128;
    const int bn = blockIdx.x * 256;     // 0..3071 within stacked W
    const int seg = bn >> 10;            // 0=q, 1=k, 2=v
    const int cn = bn & (DD - 1);

    const float* bias = (seg == 0) ? bq : (seg == 1) ? bk : bv;
    float* C = (seg == 0) ? Cq : (seg == 1) ? Ck : Cv;

    // packed source bases
    const uint8_t* axh = g_xpack_hi + (size_t)blockIdx.y * NCHK * TILE_PK;
    const uint8_t* axl = g_xpack_lo + (size_t)blockIdx.y * NCHK * TILE_PK;
    const uint8_t* bwh = g_wpack_hi + (size_t)(blockIdx.x * 2) * NCHK * TILE_PK;
    const uint8_t* bwl = g_wpack_lo + (size_t)(blockIdx.x * 2) * NCHK * TILE_PK;

    // ldmatrix lane-address components
    const int lr = lane & 7;
    const int g = lane >> 3;                       // 0..3
    const uint32_t a_row = warp_m * 64 + (g & 1) * 8 + lr;   // + mt*16
    const uint32_t a_koff = (g >> 1) * 8;
    const uint32_t b_row = warp_n * 64 + ((lane >> 4) << 3) + lr;  // + j*16
    const uint32_t b_koff = ((lane >> 3) & 1) * 8;

    float acc[4][8][4];
#pragma unroll
    for (int i = 0; i < 4; i++)
#pragma unroll
        for (int j = 0; j < 8; j++)
#pragma unroll
            for (int r = 0; r < 4; r++) acc[i][j][r] = 0.f;

    // mbarrier init
    if (tid == 0) {
#pragma unroll
        for (int s = 0; s < NSTAGE; s++)
            MBARRIER_INIT(smem_base + SM_MBAR + s * 8, 1);
    }
    __syncthreads();

    auto issue = [&](int ch) {
        const int s = ch % NSTAGE;
        const uint32_t mbar = smem_base + SM_MBAR + s * 8;
        const uint32_t sb = smem_base + s * STAGE_B;
        MBARRIER_EXPECT_TX(mbar, STAGE_B);
        cp_bulk(sb + ST_A_HI,         axh + (size_t)ch * TILE_PK, TILE_PK, mbar);
        cp_bulk(sb + ST_A_LO,         axl + (size_t)ch * TILE_PK, TILE_PK, mbar);
        cp_bulk(sb + ST_B_HI,         bwh + (size_t)ch * TILE_PK, TILE_PK, mbar);
        cp_bulk(sb + ST_B_HI + TILE_PK, bwh + (size_t)(NCHK + ch) * TILE_PK, TILE_PK, mbar);
        cp_bulk(sb + ST_B_LO,         bwl + (size_t)ch * TILE_PK, TILE_PK, mbar);
        cp_bulk(sb + ST_B_LO + TILE_PK, bwl + (size_t)(NCHK + ch) * TILE_PK, TILE_PK, mbar);
    };

    if (tid == 0) { issue(0); issue(1); }

    int s = 0, p = 0;
    for (int ch = 0; ch < NCHK; ch++) {
        MBARRIER_WAIT_PARITY(smem_base + SM_MBAR + s * 8, p);
        __syncthreads();                       // all threads done with ch-1's stage
        if (tid == 0 && ch + 2 < NCHK) issue(ch + 2);

        const uint32_t base = smem_base + s * STAGE_B;
#pragma unroll
        for (int ks = 0; ks < 2; ks++) {
            uint32_t ahi[4][4], alo[4][4], bhi[4][4], blo[4][4];
#pragma unroll
            for (int mt = 0; mt < 4; mt++) {
                uint32_t ar = base + (a_row + mt * 16) * ROWB
                            + (ks * 16 + a_koff) * 2;
                ldm_x4(ahi[mt], ar + ST_A_HI);
                ldm_x4(alo[mt], ar + ST_A_LO);
            }
#pragma unroll
            for (int j = 0; j < 4; j++) {             // each covers 2 n-tiles
                uint32_t br = base + (b_row + j * 16) * ROWB
                            + (ks * 16 + b_koff) * 2;
                ldm_x4(bhi[j], br + ST_B_HI);
                ldm_x4(blo[j], br + ST_B_LO);
            }
#pragma unroll
            for (int mt = 0; mt < 4; mt++)
#pragma unroll
                for (int nt = 0; nt < 8; nt++)
                    mma_bf16(acc[mt][nt], ahi[mt], &bhi[nt >> 1][(nt & 1) * 2]);
#pragma unroll
            for (int mt = 0; mt < 4; mt++)
#pragma unroll
                for (int nt = 0; nt < 8; nt++)
                    mma_bf16(acc[mt][nt], ahi[mt], &blo[nt >> 1][(nt & 1) * 2]);
#pragma unroll
            for (int mt = 0; mt < 4; mt++)
#pragma unroll
                for (int nt = 0; nt < 8; nt++)
                    mma_bf16(acc[mt][nt], alo[mt], &bhi[nt >> 1][(nt & 1) * 2]);
        }
        s++;
        if (s == NSTAGE) { s = 0; p ^= 1; }
    }

    // ---- epilogue: direct frag stores + bias --------------------------------
    const int qr = lane >> 2;           // 0..7
    const int qc = (lane & 3) * 2;      // 0,2,4,6
#pragma unroll
    for (int mt = 0; mt < 4; mt++) {
#pragma unroll
        for (int nt = 0; nt < 8; nt++) {
            const int row0 = bm + warp_m * 64 + mt * 16 + qr;
            const int col = cn + warp_n * 64 + nt * 8 + qc;
            const float2 bvv = *(const float2*)&bias[col];
            float2 v0, v1;
            v0.x = acc[mt][nt][0] + bvv.x;
            v0.y = acc[mt][nt][1] + bvv.y;
            v1.x = acc[mt][nt][2] + bvv.x;
            v1.y = acc[mt][nt][3] + bvv.y;
            *(float2*)&C[(size_t)row0 * DD + col] = v0;
            *(float2*)&C[(size_t)(row0 + 8) * DD + col] = v1;
        }
    }
}

// ---------------- chunked scan (kv = k*v computed inline) --------------------
__global__ __launch_bounds__(256) void scan1_kernel(const float* __restrict__ decay) {
    int x = blockIdx.x * blockDim.x + threadIdx.x;   // < NCH*BB*DD
    int d = x & (DD - 1);
    int b = (x >> 10) & (BB - 1);
    int c = x >> 13;
    float dec = decay[d];
    size_t base = (size_t)b * TT * DD + (size_t)c * LCH * DD + d;
    float mem = 0.f;
#pragma unroll 4
    for (int t = 0; t < LCH; t++) {
        size_t off = base + (size_t)t * DD;
        mem = fmaf(dec, mem, g_k[off] * g_v[off]);
    }
    g_finals[((size_t)c * BB + b) * DD + d] = mem;
}

__global__ __launch_bounds__(256) void scan2_kernel(const float* __restrict__ decay) {
    int x = blockIdx.x * blockDim.x + threadIdx.x;   // < BB*DD
    int d = x & (DD - 1);
    int b = x >> 10;
    float dec = decay[d];
    float pL = dec;
#pragma unroll
    for (int i = 0; i < 7; i++) pL *= pL;            // dec^128
    float carry = 0.f;
#pragma unroll
    for (int c = 0; c < NCH; c++) {
        size_t idx = ((size_t)c * BB + b) * DD + d;
        g_carries[idx] = carry;
        carry = fmaf(pL, carry, g_finals[idx]);
    }
}

__global__ __launch_bounds__(256) void scan3_kernel(const float* __restrict__ decay,
                                                    float* __restrict__ out) {
    int x = blockIdx.x * blockDim.x + threadIdx.x;
    int d = x & (DD - 1);
    int b = (x >> 10) & (BB - 1);
    int c = x >> 13;
    float dec = decay[d];
    size_t base = (size_t)b * TT * DD + (size_t)c * LCH * DD + d;
    float mem = g_carries[((size_t)c * BB + b) * DD + d];
#pragma unroll 4
    for (int t = 0; t < LCH; t++) {
        size_t off = base + (size_t)t * DD;
        mem = fmaf(dec, mem, g_k[off] * g_v[off]);
        out[off] = g_q[off] * mem;
    }
}

// ---------------- launch -----------------------------------------------------
extern "C" void kernel_launch(void* const* d_in, const int* in_sizes, int n_in,
                              void* d_out, int out_size) {
    const float* x     = (const float*)d_in[0];
    const float* Wq    = (const float*)d_in[1];
    const float* bq    = (const float*)d_in[2];
    const float* Wk    = (const float*)d_in[3];
    const float* bk    = (const float*)d_in[4];
    const float* Wv    = (const float*)d_in[5];
    const float* bv    = (const float*)d_in[6];
    const float* decay = (const float*)d_in[7];
    float* out = (float*)d_out;

    float *q_p, *k_p, *v_p;
    uint8_t *xh_p, *xl_p, *wh_p, *wl_p;
    cudaGetSymbolAddress((void**)&q_p, g_q);
    cudaGetSymbolAddress((void**)&k_p, g_k);
    cudaGetSymbolAddress((void**)&v_p, g_v);
    cudaGetSymbolAddress((void**)&xh_p, g_xpack_hi);
    cudaGetSymbolAddress((void**)&xl_p, g_xpack_lo);
    cudaGetSymbolAddress((void**)&wh_p, g_wpack_hi);
    cudaGetSymbolAddress((void**)&wl_p, g_wpack_lo);

    const int XN4 = MT * DD / 4;                 // 4M
    const int WN4 = DD * DD / 4;                 // 256K
    const size_t WSEG = (size_t)8 * NCHK * TILE_PK;   // packed bytes per W segment

    // packed hi/lo splits
    split_pack_kernel<<<XN4 / 256, 256>>>(x, xh_p, xl_p, XN4);
    split_pack_kernel<<<WN4 / 256, 256>>>(Wq, wh_p + 0 * WSEG, wl_p + 0 * WSEG, WN4);
    split_pack_kernel<<<WN4 / 256, 256>>>(Wk, wh_p + 1 * WSEG, wl_p + 1 * WSEG, WN4);
    split_pack_kernel<<<WN4 / 256, 256>>>(Wv, wh_p + 2 * WSEG, wl_p + 2 * WSEG, WN4);

    // fused QKV HMMA GEMM (single launch, N=3072, bulk-async loads)
    const int smem_bytes = NSTAGE * STAGE_B + 64;   // 184320 + mbarriers
    cudaFuncSetAttribute(gemm_qkv_kernel, cudaFuncAttributeMaxDynamicSharedMemorySize, smem_bytes);
    dim3 grid(3 * DD / 256, MT / 128);              // (12, 128) = 1536 CTAs
    gemm_qkv_kernel<<<grid, 256, smem_bytes>>>(bq, bk, bv, q_p, k_p, v_p);

    // chunked scan
    scan1_kernel<<<(NCH * BB * DD) / 256, 256>>>(decay);
    scan2_kernel<<<(BB * DD) / 256, 256>>>(decay);
    scan3_kernel<<<(NCH * BB * DD) / 256, 256>>>(decay, out);
}